// round 7
// baseline (speedup 1.0000x reference)
#include <cuda_runtime.h>
#include <cuda_bf16.h>
#include <math.h>
#include <stdint.h>

#define BB 8
#define HH 1024
#define DD 4
#define TI 16          // output rows per block
#define TJ 64          // j-tile width
#define NTILE (HH / TJ)
#define PADJ 68        // shAT row stride in floats (conflict-free)
#define NBUF 3

// Scratch (__device__ globals: allocation-guard safe)
__device__ uint32_t g_casa[HH * HH];   // packed bf16x2: lo=0.5*cos(alpha), hi=0.5*sin(alpha)
__device__ float    g_sth[BB * HH * DD];
__device__ float    g_cth[BB * HH * DD];

typedef unsigned long long u64;

__device__ __forceinline__ u64 pack2(float x, float y) {
    u64 r; asm("mov.b64 %0, {%1, %2};" : "=l"(r) : "f"(x), "f"(y)); return r;
}
__device__ __forceinline__ u64 ffma2(u64 a, u64 b, u64 c) {
    u64 d; asm("fma.rn.f32x2 %0, %1, %2, %3;" : "=l"(d) : "l"(a), "l"(b), "l"(c)); return d;
}
__device__ __forceinline__ float2 unpk2(u64 v) {
    float x, y; asm("mov.b64 {%0, %1}, %2;" : "=f"(x), "=f"(y) : "l"(v));
    return make_float2(x, y);
}
__device__ __forceinline__ void cp_async4(uint32_t s, const void* g) {
    asm volatile("cp.async.ca.shared.global [%0], [%1], 4;" :: "r"(s), "l"(g));
}
__device__ __forceinline__ void cp_async16(uint32_t s, const void* g) {
    asm volatile("cp.async.cg.shared.global [%0], [%1], 16;" :: "r"(s), "l"(g));
}
__device__ __forceinline__ void cp_commit() { asm volatile("cp.async.commit_group;"); }
__device__ __forceinline__ void cp_wait1()  { asm volatile("cp.async.wait_group 1;"); }

// ---------------------------------------------------------------------------
// Kernel 1: trig precompute. casa packed to bf16x2 (0.5 factor folded in).
// ---------------------------------------------------------------------------
__global__ void vk_trig_kernel(const float* __restrict__ alpha,
                               const float* __restrict__ theta) {
    int idx = blockIdx.x * blockDim.x + threadIdx.x;
    const int NA = HH * HH;
    const int NT = BB * HH * DD;
    if (idx < NA) {
        float s, c;
        sincosf(alpha[idx], &s, &c);
        uint32_t cb = (uint32_t)__bfloat16_as_ushort(__float2bfloat16(0.5f * c));
        uint32_t sb = (uint32_t)__bfloat16_as_ushort(__float2bfloat16(0.5f * s));
        g_casa[idx] = (sb << 16) | cb;
    } else if (idx < NA + NT) {
        int t = idx - NA;
        float s, c;
        sincosf(theta[t], &s, &c);
        g_sth[t] = s;
        g_cth[t] = c;
    }
}

// One (i,j) pair: m = relu(ar+at); w1 = m*ca'; w2 = m*sa'
// s1 += w1*s - w2*c ; s2 += w1*c + w2*s   (packed f32x2 over d-pairs)
#define KPAIR(ar, at, caf, saf, Sv, Cv, P0, P1, P2, P3)      \
    {                                                        \
        float m_  = fmaxf((ar) + (at), 0.f);                 \
        float w1_ = m_ * (caf);                              \
        float w2_ = m_ * (saf);                              \
        float n2_ = -w2_;                                    \
        u64 w1p_ = pack2(w1_, w1_);                          \
        u64 w2p_ = pack2(w2_, w2_);                          \
        u64 n2p_ = pack2(n2_, n2_);                          \
        P0 = ffma2(w1p_, (Sv).x, P0); P0 = ffma2(n2p_, (Cv).x, P0); \
        P1 = ffma2(w1p_, (Sv).y, P1); P1 = ffma2(n2p_, (Cv).y, P1); \
        P2 = ffma2(w1p_, (Cv).x, P2); P2 = ffma2(w2p_, (Sv).x, P2); \
        P3 = ffma2(w1p_, (Cv).y, P3); P3 = ffma2(w2p_, (Sv).y, P3); \
    }

// ---------------------------------------------------------------------------
// Kernel 2: main coupling. Grid (H/TI, B), block 256 = 8 warps, 2 rows/warp.
// NBUF=3 single-barrier cp.async pipeline. ALL operands staged in shared:
// A^T tile, A-row tile, bf16x2 casa tile, theta-trig tiles. Zero LDG in loop.
// ---------------------------------------------------------------------------
__global__ __launch_bounds__(256, 4)
void vk_main_kernel(const float* __restrict__ theta,
                    const float* __restrict__ gamma,
                    const float* __restrict__ A,
                    const float* __restrict__ omega,
                    const float* __restrict__ kappa,
                    float* __restrict__ out) {
    __shared__ float      shAT[NBUF][TI * PADJ]; // [ii][jj] = A[b, j0+jj, i0+ii]
    __shared__ float      shAR[NBUF][TI * TJ];   // [ii][jj] = A[b, i0+ii, j0+jj]
    __shared__ uint32_t   shCS[NBUF][TI * TJ];   // [ii][jj] = casa[i0+ii, j0+jj]
    __shared__ ulonglong2 shS[NBUF][TJ];         // sin(theta[b, j0+jj, 0..3])
    __shared__ ulonglong2 shC[NBUF][TJ];         // cos(theta[b, j0+jj, 0..3])

    const int b    = blockIdx.y;
    const int i0   = blockIdx.x * TI;
    const int tid  = threadIdx.x;
    const int warp = tid >> 5;
    const int lane = tid & 31;

    const float* Ab   = A + (size_t)b * HH * HH;
    const float* sthb = g_sth + (size_t)b * HH * DD;
    const float* cthb = g_cth + (size_t)b * HH * DD;

    const int riA = warp * 2;
    const int iA  = i0 + riA;

    // staging maps
    const int at_ii = tid & 15;      // A^T: fast gmem index over i
    const int at_jj = tid >> 4;      // 0..15
    const int rc_ii = tid >> 4;      // AR/casa: row 0..15
    const int rc_jq = tid & 15;      // float4/u32x4 chunk 0..15

    auto stage = [&](int tt, int sb) {
        const int j0_ = tt * TJ;
        // A^T tile: 4x cp.async4 per thread (gmem coalesced over ii)
        uint32_t dAT = (uint32_t)__cvta_generic_to_shared(&shAT[sb][0]);
        #pragma unroll
        for (int p = 0; p < 4; p++) {
            int jj = at_jj + p * 16;
            cp_async4(dAT + (uint32_t)(at_ii * PADJ + jj) * 4,
                      Ab + (size_t)(j0_ + jj) * HH + (i0 + at_ii));
        }
        // A-row tile: 256 float4 -> 1 cp.async16 per thread
        cp_async16((uint32_t)__cvta_generic_to_shared(&shAR[sb][0]) +
                       (uint32_t)(rc_ii * TJ + rc_jq * 4) * 4,
                   Ab + (size_t)(i0 + rc_ii) * HH + j0_ + rc_jq * 4);
        // casa tile: 256 u32x4 -> 1 cp.async16 per thread
        cp_async16((uint32_t)__cvta_generic_to_shared(&shCS[sb][0]) +
                       (uint32_t)(rc_ii * TJ + rc_jq * 4) * 4,
                   g_casa + (size_t)(i0 + rc_ii) * HH + j0_ + rc_jq * 4);
        // theta trig: tid<64 -> S, 64..127 -> C
        if (tid < TJ) {
            cp_async16((uint32_t)__cvta_generic_to_shared(&shS[sb][tid]),
                       sthb + (size_t)(j0_ + tid) * DD);
        } else if (tid < 2 * TJ) {
            cp_async16((uint32_t)__cvta_generic_to_shared(&shC[sb][tid - TJ]),
                       cthb + (size_t)(j0_ + tid - TJ) * DD);
        }
    };

    u64 A0 = 0, A1 = 0, A2 = 0, A3 = 0;  // row A: s1 d01, s1 d23, s2 d01, s2 d23
    u64 B0 = 0, B1 = 0, B2 = 0, B3 = 0;  // row B

    stage(0, 0); cp_commit();
    stage(1, 1); cp_commit();

    int s = 0;
    for (int t = 0; t < NTILE; t++) {
        cp_wait1();                 // this thread's group t complete
        __syncthreads();            // publish tile t; all warps past tile t-1
        int s2 = s + 2; if (s2 >= NBUF) s2 -= NBUF;
        if (t + 2 < NTILE) stage(t + 2, s2);  // into buffer freed by t-1
        cp_commit();

        const float*      bAT  = shAT[s];
        const float*      bAR  = shAR[s];
        const uint32_t*   bCS  = shCS[s];
        const ulonglong2* bufS = shS[s];
        const ulonglong2* bufC = shC[s];

        #pragma unroll
        for (int q = 0; q < TJ / 32; q++) {
            const int jl = q * 32 + lane;
            ulonglong2 Sv = bufS[jl];                 // LDS.128, conflict-free
            ulonglong2 Cv = bufC[jl];
            float atA = bAT[riA * PADJ + jl];         // LDS.32, lane-consecutive
            float atB = bAT[(riA + 1) * PADJ + jl];
            float arA = bAR[riA * TJ + jl];
            float arB = bAR[(riA + 1) * TJ + jl];
            uint32_t csA = bCS[riA * TJ + jl];
            uint32_t csB = bCS[(riA + 1) * TJ + jl];
            float caA = __uint_as_float(csA << 16);
            float saA = __uint_as_float(csA & 0xFFFF0000u);
            float caB = __uint_as_float(csB << 16);
            float saB = __uint_as_float(csB & 0xFFFF0000u);
            KPAIR(arA, atA, caA, saA, Sv, Cv, A0, A1, A2, A3);
            KPAIR(arB, atB, caB, saB, Sv, Cv, B0, B1, B2, B3);
        }
        s = s + 1; if (s >= NBUF) s = 0;
    }

    // Unpack + warp butterfly reduction (16 scalars)
    float v[16];
    {
        float2 t2;
        t2 = unpk2(A0); v[0]  = t2.x; v[1]  = t2.y;
        t2 = unpk2(A1); v[2]  = t2.x; v[3]  = t2.y;
        t2 = unpk2(A2); v[4]  = t2.x; v[5]  = t2.y;
        t2 = unpk2(A3); v[6]  = t2.x; v[7]  = t2.y;
        t2 = unpk2(B0); v[8]  = t2.x; v[9]  = t2.y;
        t2 = unpk2(B1); v[10] = t2.x; v[11] = t2.y;
        t2 = unpk2(B2); v[12] = t2.x; v[13] = t2.y;
        t2 = unpk2(B3); v[14] = t2.x; v[15] = t2.y;
    }
    #pragma unroll
    for (int off = 16; off > 0; off >>= 1) {
        #pragma unroll
        for (int qq = 0; qq < 16; qq++)
            v[qq] += __shfl_xor_sync(0xFFFFFFFFu, v[qq], off);
    }

    if (lane < 2) {
        const int i = iA + lane;
        const float* vv = v + lane * 8;       // [s1_d0..d3, s2_d0..d3]
        const float invH = 1.0f / (float)HH;  // K_COUP=1, DT=1, 0.5 folded
        const size_t base = ((size_t)b * HH + i) * DD;
        float4 si4 = *(const float4*)(g_sth + base);
        float4 ci4 = *(const float4*)(g_cth + base);
        float4 tp4 = *(const float4*)(theta + base);
        float4 om4 = *(const float4*)(omega + (size_t)i * DD);
        float4 kp4 = *(const float4*)(kappa + (size_t)i * DD);
        float g = gamma[(size_t)b * HH + i];

        float4 rr;
        rr.x = tp4.x + om4.x + invH * (ci4.x * vv[0] - si4.x * vv[4]) + kp4.x * (g - tp4.x);
        rr.y = tp4.y + om4.y + invH * (ci4.y * vv[1] - si4.y * vv[5]) + kp4.y * (g - tp4.y);
        rr.z = tp4.z + om4.z + invH * (ci4.z * vv[2] - si4.z * vv[6]) + kp4.z * (g - tp4.z);
        rr.w = tp4.w + om4.w + invH * (ci4.w * vv[3] - si4.w * vv[7]) + kp4.w * (g - tp4.w);
        *(float4*)(out + base) = rr;
    }
}

extern "C" void kernel_launch(void* const* d_in, const int* in_sizes, int n_in,
                              void* d_out, int out_size) {
    const float* theta = (const float*)d_in[0];  // [B,H,D]
    const float* gamma = (const float*)d_in[1];  // [B,H]
    const float* A     = (const float*)d_in[2];  // [B,H,H]
    const float* omega = (const float*)d_in[3];  // [H,D]
    const float* kappa = (const float*)d_in[4];  // [H,D]
    const float* alpha = (const float*)d_in[5];  // [H,H]
    float* out = (float*)d_out;

    {
        int n = HH * HH + BB * HH * DD;
        int threads = 256;
        int blocks = (n + threads - 1) / threads;
        vk_trig_kernel<<<blocks, threads>>>(alpha, theta);
    }
    {
        dim3 grid(HH / TI, BB);
        vk_main_kernel<<<grid, 256>>>(theta, gamma, A, omega, kappa, out);
    }
}

// round 8
// speedup vs baseline: 1.1156x; 1.1156x over previous
#include <cuda_runtime.h>
#include <math.h>
#include <stdint.h>

#define BB 8
#define HH 1024
#define DD 4
#define TI 8           // output rows per block
#define TJ 128         // j-tile width
#define PADI 9         // padded i-stride of transpose tile (odd -> conflict-free)
#define NBUF 3         // pipeline stages
#define NTILE (HH / TJ)
#define NTHR 128

// Scratch (__device__ globals: allocation-guard safe)
__device__ float2 g_casa[HH * HH];     // (0.5*cos(alpha), 0.5*sin(alpha))
__device__ float  g_sth[BB * HH * DD]; // sin(theta)
__device__ float  g_cth[BB * HH * DD]; // cos(theta)

typedef unsigned long long u64;

__device__ __forceinline__ u64 pack2(float x, float y) {
    u64 r; asm("mov.b64 %0, {%1, %2};" : "=l"(r) : "f"(x), "f"(y)); return r;
}
__device__ __forceinline__ u64 ffma2(u64 a, u64 b, u64 c) {
    u64 d; asm("fma.rn.f32x2 %0, %1, %2, %3;" : "=l"(d) : "l"(a), "l"(b), "l"(c)); return d;
}
__device__ __forceinline__ float2 unpk2(u64 v) {
    float x, y; asm("mov.b64 {%0, %1}, %2;" : "=f"(x), "=f"(y) : "l"(v));
    return make_float2(x, y);
}
__device__ __forceinline__ void cp_async4(uint32_t s, const void* g) {
    asm volatile("cp.async.ca.shared.global [%0], [%1], 4;" :: "r"(s), "l"(g));
}
__device__ __forceinline__ void cp_async16(uint32_t s, const void* g) {
    asm volatile("cp.async.cg.shared.global [%0], [%1], 16;" :: "r"(s), "l"(g));
}
__device__ __forceinline__ void cp_commit() { asm volatile("cp.async.commit_group;"); }
__device__ __forceinline__ void cp_wait1()  { asm volatile("cp.async.wait_group 1;"); }

// ---------------------------------------------------------------------------
// Kernel 1: trig precompute (0.5 of symmetrization folded into alpha tables)
// ---------------------------------------------------------------------------
__global__ void vk_trig_kernel(const float* __restrict__ alpha,
                               const float* __restrict__ theta) {
    int idx = blockIdx.x * blockDim.x + threadIdx.x;
    const int NA = HH * HH;
    const int NT = BB * HH * DD;
    if (idx < NA) {
        float s, c;
        sincosf(alpha[idx], &s, &c);
        g_casa[idx] = make_float2(0.5f * c, 0.5f * s);
    } else if (idx < NA + NT) {
        int t = idx - NA;
        float s, c;
        sincosf(theta[t], &s, &c);
        g_sth[t] = s;
        g_cth[t] = c;
    }
}

// One (i,j) pair: m = relu(ar+at); w1 = m*ca'; w2 = m*sa'
// s1 += w1*s - w2*c ; s2 += w1*c + w2*s   (packed f32x2 over d-pairs)
#define KPAIR(ar, at, cs, Sv, Cv, P0, P1, P2, P3)            \
    {                                                        \
        float m_  = fmaxf((ar) + (at), 0.f);                 \
        float w1_ = m_ * (cs).x;                             \
        float w2_ = m_ * (cs).y;                             \
        float n2_ = -w2_;                                    \
        u64 w1p_ = pack2(w1_, w1_);                          \
        u64 w2p_ = pack2(w2_, w2_);                          \
        u64 n2p_ = pack2(n2_, n2_);                          \
        P0 = ffma2(w1p_, (Sv).x, P0); P0 = ffma2(n2p_, (Cv).x, P0); \
        P1 = ffma2(w1p_, (Sv).y, P1); P1 = ffma2(n2p_, (Cv).y, P1); \
        P2 = ffma2(w1p_, (Cv).x, P2); P2 = ffma2(w2p_, (Sv).x, P2); \
        P3 = ffma2(w1p_, (Cv).y, P3); P3 = ffma2(w2p_, (Sv).y, P3); \
    }

// ---------------------------------------------------------------------------
// Kernel 2: main coupling. Grid (H/TI, B) = (128, 8) -> 1024 CTAs of 128 thr,
// 4 warps, 2 rows/warp. NBUF=3 single-barrier cp.async pipeline for the
// A-transpose tile + theta-trig tiles; A-row + casa via direct coalesced LDG.
// ---------------------------------------------------------------------------
__global__ __launch_bounds__(NTHR, 8)
void vk_main_kernel(const float* __restrict__ theta,
                    const float* __restrict__ gamma,
                    const float* __restrict__ A,
                    const float* __restrict__ omega,
                    const float* __restrict__ kappa,
                    float* __restrict__ out) {
    __shared__ float      shA[NBUF][TJ * PADI];  // [jj*PADI + ii] = A[b, j0+jj, i0+ii]
    __shared__ ulonglong2 shS[NBUF][TJ];         // sin(theta[b, j0+jj, 0..3])
    __shared__ ulonglong2 shC[NBUF][TJ];         // cos(theta[b, j0+jj, 0..3])

    const int b    = blockIdx.y;
    const int i0   = blockIdx.x * TI;
    const int tid  = threadIdx.x;
    const int warp = tid >> 5;
    const int lane = tid & 31;

    const float* Ab   = A + (size_t)b * HH * HH;
    const float* sthb = g_sth + (size_t)b * HH * DD;
    const float* cthb = g_cth + (size_t)b * HH * DD;

    const int riA = warp * 2;         // local row indices (4 warps x 2 rows = 8)
    const int iA  = i0 + riA;
    const float*  ArowA = Ab + (size_t)iA * HH;
    const float*  ArowB = ArowA + HH;
    const float2* csA   = g_casa + (size_t)iA * HH;
    const float2* csB   = csA + HH;

    // staging thread mapping for A^T tile: 128x8 elems, 8 per thread
    const int s_ii = tid & 7;
    const int s_jj = tid >> 3;        // 0..15

    auto stage = [&](int tt, int sb) {
        const int j0_ = tt * TJ;
        uint32_t dA_ = (uint32_t)__cvta_generic_to_shared(&shA[sb][0]);
        #pragma unroll
        for (int p_ = 0; p_ < 8; p_++) {
            int jj_ = s_jj + p_ * 16;
            cp_async4(dA_ + (uint32_t)(jj_ * PADI + s_ii) * 4,
                      Ab + (size_t)(j0_ + jj_) * HH + (i0 + s_ii));
        }
        // theta trig: each thread stages one S row and one C row (128 each)
        cp_async16((uint32_t)__cvta_generic_to_shared(&shS[sb][tid]),
                   sthb + (size_t)(j0_ + tid) * DD);
        cp_async16((uint32_t)__cvta_generic_to_shared(&shC[sb][tid]),
                   cthb + (size_t)(j0_ + tid) * DD);
    };

    u64 A0 = 0, A1 = 0, A2 = 0, A3 = 0;  // row A: s1 d01, s1 d23, s2 d01, s2 d23
    u64 B0 = 0, B1 = 0, B2 = 0, B3 = 0;  // row B

    stage(0, 0); cp_commit();
    stage(1, 1); cp_commit();

    int s = 0;
    for (int t = 0; t < NTILE; t++) {
        cp_wait1();                 // tile t resident (t+1 may be in flight)
        __syncthreads();
        // issue tile t+2 into the buffer freed by tile t-1 (all warps are past it)
        int s2 = s + 2; if (s2 >= NBUF) s2 -= NBUF;
        if (t + 2 < NTILE) stage(t + 2, s2);
        cp_commit();                // always commit: keeps the group FIFO depth fixed

        const float*      bufA = shA[s];
        const ulonglong2* bufS = shS[s];
        const ulonglong2* bufC = shC[s];
        const int j0 = t * TJ;

        #pragma unroll
        for (int q = 0; q < 4; q++) {
            const int jl = q * 32 + lane;
            const int j  = j0 + jl;
            ulonglong2 Sv = bufS[jl];            // LDS.128, conflict-free
            ulonglong2 Cv = bufC[jl];
            float  atA = bufA[jl * PADI + riA];  // LDS.32, conflict-free (odd stride)
            float  atB = bufA[jl * PADI + riA + 1];
            float  arA = ArowA[j];               // coalesced LDG.32
            float  arB = ArowB[j];
            float2 caA = csA[j];                 // coalesced LDG.64
            float2 caB = csB[j];
            KPAIR(arA, atA, caA, Sv, Cv, A0, A1, A2, A3);
            KPAIR(arB, atB, caB, Sv, Cv, B0, B1, B2, B3);
        }
        s = s + 1; if (s >= NBUF) s = 0;
    }

    // Unpack + warp butterfly reduction (16 scalars)
    float v[16];
    {
        float2 t2;
        t2 = unpk2(A0); v[0]  = t2.x; v[1]  = t2.y;
        t2 = unpk2(A1); v[2]  = t2.x; v[3]  = t2.y;
        t2 = unpk2(A2); v[4]  = t2.x; v[5]  = t2.y;
        t2 = unpk2(A3); v[6]  = t2.x; v[7]  = t2.y;
        t2 = unpk2(B0); v[8]  = t2.x; v[9]  = t2.y;
        t2 = unpk2(B1); v[10] = t2.x; v[11] = t2.y;
        t2 = unpk2(B2); v[12] = t2.x; v[13] = t2.y;
        t2 = unpk2(B3); v[14] = t2.x; v[15] = t2.y;
    }
    #pragma unroll
    for (int off = 16; off > 0; off >>= 1) {
        #pragma unroll
        for (int qq = 0; qq < 16; qq++)
            v[qq] += __shfl_xor_sync(0xFFFFFFFFu, v[qq], off);
    }

    if (lane < 2) {
        const int i = iA + lane;
        const float* vv = v + lane * 8;       // [s1_d0..d3, s2_d0..d3]
        const float invH = 1.0f / (float)HH;  // K_COUP=1, DT=1, 0.5 folded
        const size_t base = ((size_t)b * HH + i) * DD;
        float4 si4 = *(const float4*)(g_sth + base);
        float4 ci4 = *(const float4*)(g_cth + base);
        float4 tp4 = *(const float4*)(theta + base);
        float4 om4 = *(const float4*)(omega + (size_t)i * DD);
        float4 kp4 = *(const float4*)(kappa + (size_t)i * DD);
        float g = gamma[(size_t)b * HH + i];

        float4 rr;
        rr.x = tp4.x + om4.x + invH * (ci4.x * vv[0] - si4.x * vv[4]) + kp4.x * (g - tp4.x);
        rr.y = tp4.y + om4.y + invH * (ci4.y * vv[1] - si4.y * vv[5]) + kp4.y * (g - tp4.y);
        rr.z = tp4.z + om4.z + invH * (ci4.z * vv[2] - si4.z * vv[6]) + kp4.z * (g - tp4.z);
        rr.w = tp4.w + om4.w + invH * (ci4.w * vv[3] - si4.w * vv[7]) + kp4.w * (g - tp4.w);
        *(float4*)(out + base) = rr;
    }
}

extern "C" void kernel_launch(void* const* d_in, const int* in_sizes, int n_in,
                              void* d_out, int out_size) {
    const float* theta = (const float*)d_in[0];  // [B,H,D]
    const float* gamma = (const float*)d_in[1];  // [B,H]
    const float* A     = (const float*)d_in[2];  // [B,H,H]
    const float* omega = (const float*)d_in[3];  // [H,D]
    const float* kappa = (const float*)d_in[4];  // [H,D]
    const float* alpha = (const float*)d_in[5];  // [H,H]
    float* out = (float*)d_out;

    {
        int n = HH * HH + BB * HH * DD;
        int threads = 256;
        int blocks = (n + threads - 1) / threads;
        vk_trig_kernel<<<blocks, threads>>>(alpha, theta);
    }
    {
        dim3 grid(HH / TI, BB);
        vk_main_kernel<<<grid, NTHR>>>(theta, gamma, A, omega, kappa, out);
    }
}